// round 1
// baseline (speedup 1.0000x reference)
#include <cuda_runtime.h>
#include <cstdint>

#define NN        8192
#define KSEL      64
#define NTHREADS  256
#define EQ_CAP    512

// Warp-aggregated shared-memory histogram add: one atomic per distinct bin
// per warp instead of per lane (the data clusters heavily in a few exponent
// bins, so naive atomics would serialize).
__device__ __forceinline__ void hist_add(uint32_t* hist, uint32_t bin, bool pred, int lane) {
    unsigned act = __ballot_sync(0xffffffffu, pred);
    if (pred) {
        unsigned same   = __match_any_sync(act, bin);
        int      leader = __ffs(same) - 1;
        if (lane == leader) atomicAdd(&hist[bin], (uint32_t)__popc(same));
    }
}

extern __shared__ uint32_t sdata[];   // NN uint32 (relu'd float bits)

__global__ __launch_bounds__(NTHREADS)
void topk_mask_kernel(const float* __restrict__ A, float* __restrict__ out)
{
    __shared__ uint32_t hist[256];
    __shared__ uint32_t suffix[256];
    __shared__ uint32_t wsum[8];
    __shared__ uint32_t sh_prefix;   // accumulated bits of the k-th largest value
    __shared__ uint32_t sh_k;        // remaining rank within current bucket
    __shared__ uint32_t sh_flag;     // 1 if row has fewer than KSEL positives
    __shared__ uint32_t eq_idx[EQ_CAP];
    __shared__ uint32_t eq_count;

    const int    tid  = threadIdx.x;
    const int    lane = tid & 31;
    const size_t row  = blockIdx.x;

    const float4* arow = reinterpret_cast<const float4*>(A + row * (size_t)NN);
    float4*       orow = reinterpret_cast<float4*>(out + row * (size_t)NN);
    uint4*        s4   = reinterpret_cast<uint4*>(sdata);

    hist[tid] = 0;
    if (tid == 0) { sh_prefix = 0; sh_k = KSEL; sh_flag = 0; eq_count = 0; }
    __syncthreads();

    // ---- Load + relu + fused pass-1 histogram (top byte), skipping zeros ----
    #pragma unroll
    for (int i = tid; i < NN / 4; i += NTHREADS) {
        float4 v = arow[i];
        uint32_t b0 = (v.x > 0.0f) ? __float_as_uint(v.x) : 0u;
        uint32_t b1 = (v.y > 0.0f) ? __float_as_uint(v.y) : 0u;
        uint32_t b2 = (v.z > 0.0f) ? __float_as_uint(v.z) : 0u;
        uint32_t b3 = (v.w > 0.0f) ? __float_as_uint(v.w) : 0u;
        s4[i] = make_uint4(b0, b1, b2, b3);
        hist_add(hist, b0 >> 24, b0 != 0u, lane);
        hist_add(hist, b1 >> 24, b1 != 0u, lane);
        hist_add(hist, b2 >> 24, b2 != 0u, lane);
        hist_add(hist, b3 >> 24, b3 != 0u, lane);
    }
    __syncthreads();

    // ---- 4-pass 8-bit radix select for the KSEL-th largest (exact) ----
    for (int pass = 0; pass < 4; ++pass) {
        const int shift = 24 - 8 * pass;

        if (pass > 0) {
            const uint32_t pfx       = sh_prefix;
            const uint32_t maskAbove = 0xFFFFFFFFu << (shift + 8);
            for (int i = tid; i < NN / 4; i += NTHREADS) {
                uint4 b = s4[i];
                hist_add(hist, (b.x >> shift) & 255u, b.x != 0u && (b.x & maskAbove) == pfx, lane);
                hist_add(hist, (b.y >> shift) & 255u, b.y != 0u && (b.y & maskAbove) == pfx, lane);
                hist_add(hist, (b.z >> shift) & 255u, b.z != 0u && (b.z & maskAbove) == pfx, lane);
                hist_add(hist, (b.w >> shift) & 255u, b.w != 0u && (b.w & maskAbove) == pfx, lane);
            }
            __syncthreads();
        }

        const uint32_t kcur = sh_k;     // read before any write this pass
        uint32_t v = hist[tid];
        hist[tid] = 0;                  // clear own bin for next pass (safe: barrier-separated)

        // warp-level inclusive suffix scan over this warp's 32 bins
        #pragma unroll
        for (int d = 1; d < 32; d <<= 1) {
            uint32_t o = __shfl_down_sync(0xffffffffu, v, d);
            if (lane + d < 32) v += o;
        }
        if (lane == 0) wsum[tid >> 5] = v;   // warp total (= suffix at warp's first bin)
        __syncthreads();

        uint32_t hi = 0;
        for (int w = (tid >> 5) + 1; w < 8; ++w) hi += wsum[w];
        const uint32_t s = v + hi;           // suffix sum: count of values with digit >= tid
        suffix[tid] = s;
        __syncthreads();

        if (pass == 0 && tid == 0 && suffix[0] < kcur) sh_flag = 1;  // <KSEL positives

        const uint32_t nxt = (tid == 255) ? 0u : suffix[tid + 1];
        if (s >= kcur && nxt < kcur) {       // exactly one thread matches
            sh_prefix |= ((uint32_t)tid) << shift;
            sh_k       = kcur - nxt;         // remaining rank inside this bucket
        }
        __syncthreads();
        if (sh_flag) break;                  // uniform: degenerate row, T = 0
    }

    const uint32_t T    = sh_prefix;         // bits of the KSEL-th largest value
    const uint32_t need = sh_k;              // number of ==T elements to keep
    const bool     deg  = (sh_flag != 0);

    // ---- Output sweep: strict keep v > T, record ties; coalesced stores ----
    for (int i = tid; i < NN / 4; i += NTHREADS) {
        uint4 b = s4[i];
        float4 o;
        if (deg) {
            // fewer than KSEL positives: every positive is in the top-k
            o.x = __uint_as_float(b.x);
            o.y = __uint_as_float(b.y);
            o.z = __uint_as_float(b.z);
            o.w = __uint_as_float(b.w);
        } else {
            o.x = (b.x > T) ? __uint_as_float(b.x) : 0.0f;
            o.y = (b.y > T) ? __uint_as_float(b.y) : 0.0f;
            o.z = (b.z > T) ? __uint_as_float(b.z) : 0.0f;
            o.w = (b.w > T) ? __uint_as_float(b.w) : 0.0f;
            if (b.x == T) { uint32_t p = atomicAdd(&eq_count, 1u); if (p < EQ_CAP) eq_idx[p] = 4u * i + 0u; }
            if (b.y == T) { uint32_t p = atomicAdd(&eq_count, 1u); if (p < EQ_CAP) eq_idx[p] = 4u * i + 1u; }
            if (b.z == T) { uint32_t p = atomicAdd(&eq_count, 1u); if (p < EQ_CAP) eq_idx[p] = 4u * i + 2u; }
            if (b.w == T) { uint32_t p = atomicAdd(&eq_count, 1u); if (p < EQ_CAP) eq_idx[p] = 4u * i + 3u; }
        }
        orow[i] = o;
    }
    __syncthreads();

    // ---- Tie fix-up: keep the `need` ties with smallest indices (top_k order) ----
    if (!deg) {
        const uint32_t E = eq_count;
        if (E <= EQ_CAP) {
            for (uint32_t j = tid; j < E; j += NTHREADS) {
                const uint32_t my = eq_idx[j];
                uint32_t rank = 0;
                for (uint32_t m = 0; m < E; ++m) rank += (eq_idx[m] < my) ? 1u : 0u;
                if (rank < need) out[row * (size_t)NN + my] = __uint_as_float(T);
            }
        } else if (tid == 0) {
            // Robustness fallback (unreachable for continuous random input)
            uint32_t cnt = 0;
            for (int i = 0; i < NN; ++i) {
                if (sdata[i] == T) {
                    if (cnt < need) out[row * (size_t)NN + i] = __uint_as_float(T);
                    ++cnt;
                }
            }
        }
    }
}

extern "C" void kernel_launch(void* const* d_in, const int* in_sizes, int n_in,
                              void* d_out, int out_size) {
    const float* A   = (const float*)d_in[0];
    float*       out = (float*)d_out;
    (void)in_sizes; (void)n_in; (void)out_size;   // idx (d_in[1]) is unused by the reference
    topk_mask_kernel<<<NN, NTHREADS, NN * sizeof(uint32_t)>>>(A, out);
}